// round 5
// baseline (speedup 1.0000x reference)
#include <cuda_runtime.h>

// UnPooling (max-unpool 2x2): x [16,128,128,256] f32, pooled [16,64,64,256] f32
// out [16,128,128,256] f32: max(pooled,0) at argmax slot of each 2x2 window, else 0.
//
// NHWC, hardcoded: N=16, H=128, W=128, C=256, Hp=64, Wp=64.
// Persistent single-wave grid-stride: 592 CTAs (148 SM x 4) x 512 thr, 28 regs
// -> full occupancy, no wave transitions, no tail wave.
// CV = C/4 = 64 float4 per pixel; x row stride 8192, col stride 64 (float4 units).

#define TOTAL   (16 * 64 * 64 * 64)   // pooled float4 count = 4,194,304
#define NTHREADS (592 * 512)

__global__ __launch_bounds__(512) void unpool_kernel(const float4* __restrict__ x,
                                                     const float4* __restrict__ pooled,
                                                     float4* __restrict__ out)
{
    int tid0 = blockIdx.x * 512 + threadIdx.x;

    for (int tid = tid0; tid < TOTAL; tid += NTHREADS) {
        // tid linear over pooled in float4 units: ((n*Hp+hp)*Wp+wp)*CV + cv
        int cv = tid & 63;          // CV = 64
        int wp = (tid >> 6) & 63;   // Wp = 64
        int hp = (tid >> 12) & 63;  // Hp = 64
        int n  = tid >> 18;

        // base float4 index into x/out at (n, 2*hp, 2*wp, cv)
        int b = ((n * 128 + 2 * hp) * 128 + 2 * wp) * 64 + cv;

        float4 v00 = x[b];
        float4 v01 = x[b + 64];      // (dh=0, dw=1)
        float4 v10 = x[b + 8192];    // (dh=1, dw=0)
        float4 v11 = x[b + 8256];    // (dh=1, dw=1)
        float4 p   = pooled[tid];

        float4 o00, o01, o10, o11;

        // Row-major (dh,dw) order, first-max tie-break => strict '>' for later slots.
#define UNPOOL_COMP(F)                                                \
        {                                                             \
            float t0 = v00.F, t1 = v01.F, t2 = v10.F, t3 = v11.F;     \
            int   idx = 0;                                            \
            float best = t0;                                          \
            if (t1 > best) { best = t1; idx = 1; }                    \
            if (t2 > best) { best = t2; idx = 2; }                    \
            if (t3 > best) { best = t3; idx = 3; }                    \
            float pv = fmaxf(p.F, 0.0f);                              \
            o00.F = (idx == 0) ? pv : 0.0f;                           \
            o01.F = (idx == 1) ? pv : 0.0f;                           \
            o10.F = (idx == 2) ? pv : 0.0f;                           \
            o11.F = (idx == 3) ? pv : 0.0f;                           \
        }

        UNPOOL_COMP(x)
        UNPOOL_COMP(y)
        UNPOOL_COMP(z)
        UNPOOL_COMP(w)
#undef UNPOOL_COMP

        out[b]        = o00;
        out[b + 64]   = o01;
        out[b + 8192] = o10;
        out[b + 8256] = o11;
    }
}

extern "C" void kernel_launch(void* const* d_in, const int* in_sizes, int n_in,
                              void* d_out, int out_size)
{
    const float4* x      = (const float4*)d_in[0];
    const float4* pooled = (const float4*)d_in[1];
    float4*       out    = (float4*)d_out;

    unpool_kernel<<<592, 512>>>(x, pooled, out);
}

// round 6
// speedup vs baseline: 1.1133x; 1.1133x over previous
#include <cuda_runtime.h>

// UnPooling (max-unpool 2x2): x [16,128,128,256] f32, pooled [16,64,64,256] f32
// out [16,128,128,256] f32: max(pooled,0) at argmax slot of each 2x2 window, else 0.
//
// NHWC, hardcoded: N=16, H=128, W=128, C=256, Hp=64, Wp=64.
// FINAL (proven-best across R1-R5 sweep): flat launch, 128-bit accesses,
// 28 regs, block 512. Kernel is at the HBM roofline (~6.6 TB/s, DRAM ~84%);
// streaming hints (R2), 256-bit ops (R3), and persistent grid (R5) all
// measured neutral or worse.
// CV = C/4 = 64 float4 per pixel; x row stride 8192, col stride 64 (float4 units).

__global__ __launch_bounds__(512) void unpool_kernel(const float4* __restrict__ x,
                                                     const float4* __restrict__ pooled,
                                                     float4* __restrict__ out,
                                                     int total)
{
    int tid = blockIdx.x * blockDim.x + threadIdx.x;
    if (tid >= total) return;

    // tid linear over pooled in float4 units: ((n*Hp+hp)*Wp+wp)*CV + cv
    int cv = tid & 63;          // CV = 64
    int wp = (tid >> 6) & 63;   // Wp = 64
    int hp = (tid >> 12) & 63;  // Hp = 64
    int n  = tid >> 18;

    // base float4 index into x/out at (n, 2*hp, 2*wp, cv)
    int b = ((n * 128 + 2 * hp) * 128 + 2 * wp) * 64 + cv;

    float4 v00 = x[b];
    float4 v01 = x[b + 64];      // (dh=0, dw=1)
    float4 v10 = x[b + 8192];    // (dh=1, dw=0)
    float4 v11 = x[b + 8256];    // (dh=1, dw=1)
    float4 p   = pooled[tid];

    float4 o00, o01, o10, o11;

    // Row-major (dh,dw) order, first-max tie-break => strict '>' for later slots.
#define UNPOOL_COMP(F)                                                \
    {                                                                 \
        float t0 = v00.F, t1 = v01.F, t2 = v10.F, t3 = v11.F;         \
        int   idx = 0;                                                \
        float best = t0;                                              \
        if (t1 > best) { best = t1; idx = 1; }                        \
        if (t2 > best) { best = t2; idx = 2; }                        \
        if (t3 > best) { best = t3; idx = 3; }                        \
        float pv = fmaxf(p.F, 0.0f);                                  \
        o00.F = (idx == 0) ? pv : 0.0f;                               \
        o01.F = (idx == 1) ? pv : 0.0f;                               \
        o10.F = (idx == 2) ? pv : 0.0f;                               \
        o11.F = (idx == 3) ? pv : 0.0f;                               \
    }

    UNPOOL_COMP(x)
    UNPOOL_COMP(y)
    UNPOOL_COMP(z)
    UNPOOL_COMP(w)
#undef UNPOOL_COMP

    out[b]        = o00;
    out[b + 64]   = o01;
    out[b + 8192] = o10;
    out[b + 8256] = o11;
}

extern "C" void kernel_launch(void* const* d_in, const int* in_sizes, int n_in,
                              void* d_out, int out_size)
{
    const float4* x      = (const float4*)d_in[0];
    const float4* pooled = (const float4*)d_in[1];
    float4*       out    = (float4*)d_out;

    const int total = 16 * 64 * 64 * 64;   // pooled float4 count = 4,194,304
    const int threads = 512;
    const int blocks  = (total + threads - 1) / threads;
    unpool_kernel<<<blocks, threads>>>(x, pooled, out, total);
}

// round 7
// speedup vs baseline: 1.1212x; 1.0071x over previous
#include <cuda_runtime.h>

// UnPooling (max-unpool 2x2): x [16,128,128,256] f32, pooled [16,64,64,256] f32
// out [16,128,128,256] f32: max(pooled,0) at argmax slot of each 2x2 window, else 0.
//
// NHWC, hardcoded: N=16, H=128, W=128, C=256, Hp=64, Wp=64.
// FINAL (proven-best across R1-R6 sweep): flat launch, 128-bit accesses,
// 28 regs, block 512. At the HBM roofline: 82.4us kernel, 6.68 TB/s (83.5%
// of spec), DRAM busy 84.3%. Ruled out: streaming hints (neutral), 256-bit
// accesses (regs 46 -> occupancy loss), persistent grid (MLP/page-locality
// loss), memset+sparse-scatter (write-allocate RMW adds ~536 MB traffic).
// CV = C/4 = 64 float4 per pixel; x row stride 8192, col stride 64 (float4 units).

__global__ __launch_bounds__(512) void unpool_kernel(const float4* __restrict__ x,
                                                     const float4* __restrict__ pooled,
                                                     float4* __restrict__ out,
                                                     int total)
{
    int tid = blockIdx.x * blockDim.x + threadIdx.x;
    if (tid >= total) return;

    // tid linear over pooled in float4 units: ((n*Hp+hp)*Wp+wp)*CV + cv
    int cv = tid & 63;          // CV = 64
    int wp = (tid >> 6) & 63;   // Wp = 64
    int hp = (tid >> 12) & 63;  // Hp = 64
    int n  = tid >> 18;

    // base float4 index into x/out at (n, 2*hp, 2*wp, cv)
    int b = ((n * 128 + 2 * hp) * 128 + 2 * wp) * 64 + cv;

    float4 v00 = x[b];
    float4 v01 = x[b + 64];      // (dh=0, dw=1)
    float4 v10 = x[b + 8192];    // (dh=1, dw=0)
    float4 v11 = x[b + 8256];    // (dh=1, dw=1)
    float4 p   = pooled[tid];

    float4 o00, o01, o10, o11;

    // Row-major (dh,dw) order, first-max tie-break => strict '>' for later slots.
#define UNPOOL_COMP(F)                                                \
    {                                                                 \
        float t0 = v00.F, t1 = v01.F, t2 = v10.F, t3 = v11.F;         \
        int   idx = 0;                                                \
        float best = t0;                                              \
        if (t1 > best) { best = t1; idx = 1; }                        \
        if (t2 > best) { best = t2; idx = 2; }                        \
        if (t3 > best) { best = t3; idx = 3; }                        \
        float pv = fmaxf(p.F, 0.0f);                                  \
        o00.F = (idx == 0) ? pv : 0.0f;                               \
        o01.F = (idx == 1) ? pv : 0.0f;                               \
        o10.F = (idx == 2) ? pv : 0.0f;                               \
        o11.F = (idx == 3) ? pv : 0.0f;                               \
    }

    UNPOOL_COMP(x)
    UNPOOL_COMP(y)
    UNPOOL_COMP(z)
    UNPOOL_COMP(w)
#undef UNPOOL_COMP

    out[b]        = o00;
    out[b + 64]   = o01;
    out[b + 8192] = o10;
    out[b + 8256] = o11;
}

extern "C" void kernel_launch(void* const* d_in, const int* in_sizes, int n_in,
                              void* d_out, int out_size)
{
    const float4* x      = (const float4*)d_in[0];
    const float4* pooled = (const float4*)d_in[1];
    float4*       out    = (float4*)d_out;

    const int total = 16 * 64 * 64 * 64;   // pooled float4 count = 4,194,304
    const int threads = 512;
    const int blocks  = (total + threads - 1) / threads;
    unpool_kernel<<<blocks, threads>>>(x, pooled, out, total);
}